// round 15
// baseline (speedup 1.0000x reference)
#include <cuda_runtime.h>
#include <cuda_fp16.h>
#include <math.h>
#include <stdint.h>

// Problem constants
constexpr int B_   = 2;
constexpr int L_   = 2048;
constexpr int D_   = 1024;
constexpr int H_   = 16;
constexpr int HD_  = 64;
constexpr int WIN_ = 256;
constexpr int M_   = B_ * L_;   // 4096 rows
constexpr int K_   = D_;        // 1024 reduction dim

// Scratch (allocation-free: __device__ globals)
__device__ __half g_qh [(size_t)B_ * H_ * L_ * HD_];   // q fp16, roped, pre-scaled 1/8
__device__ __half g_kh [(size_t)B_ * H_ * L_ * HD_];   // k fp16, roped
__device__ __half g_vth[(size_t)B_ * H_ * HD_ * L_];   // v fp16 transposed [b,h,d,l]

__device__ __half g_xh [(size_t)M_ * K_];
__device__ __half g_wh [(size_t)4 * K_ * K_];          // Wq,Wk,Wv,Wo fp16
__device__ __half g_oh [(size_t)M_ * K_];              // attn out fp16

// fp16 m16n8k16 mma (baseline PTX, works on plain sm_103 target)
#define MMA16816H(d, a, b) \
    asm volatile("mma.sync.aligned.m16n8k16.row.col.f32.f16.f16.f32 " \
        "{%0,%1,%2,%3}, {%4,%5,%6,%7}, {%8,%9}, {%0,%1,%2,%3};" \
        : "+f"((d)[0]), "+f"((d)[1]), "+f"((d)[2]), "+f"((d)[3]) \
        : "r"((a)[0]), "r"((a)[1]), "r"((a)[2]), "r"((a)[3]), \
          "r"((b)[0]), "r"((b)[1]))

#define LDSM_X4(r0, r1, r2, r3, addr) \
    asm volatile("ldmatrix.sync.aligned.m8n8.x4.shared.b16 {%0,%1,%2,%3}, [%4];" \
        : "=r"(r0), "=r"(r1), "=r"(r2), "=r"(r3) : "r"(addr))

#define CP_ASYNC16(smaddr, gptr) \
    asm volatile("cp.async.cg.shared.global [%0], [%1], 16;" :: "r"(smaddr), "l"(gptr))
#define CP_COMMIT() asm volatile("cp.async.commit_group;" ::: "memory")
#define CP_WAIT(n)  asm volatile("cp.async.wait_group %0;" :: "n"(n) : "memory")

__device__ __forceinline__ uint32_t smem_u32(const void* p) {
    uint32_t a;
    asm("{ .reg .u64 t; cvta.to.shared.u64 t, %1; cvt.u32.u64 %0, t; }" : "=r"(a) : "l"(p));
    return a;
}
__device__ __forceinline__ uint32_t pack_h2(float a, float b) {
    __half2 h = __floats2half2_rn(a, b);
    return *(uint32_t*)&h;
}

// ===========================================================================
// convert x (4 chunks) + all 4 W's to fp16 in ONE launch. grid=(1024, 8).
// ===========================================================================
__global__ __launch_bounds__(256) void convert_all_kernel(
    const float* __restrict__ x,
    const float* __restrict__ W0, const float* __restrict__ W1,
    const float* __restrict__ W2, const float* __restrict__ W3,
    __half* __restrict__ wh, __half* __restrict__ xh)
{
    const int y = blockIdx.y;
    const float* src;
    __half* dst;
    if (y < 4) {
        src = (y == 0) ? W0 : (y == 1) ? W1 : (y == 2) ? W2 : W3;
        dst = wh + (size_t)y * K_ * K_;
    } else {
        src = x + (size_t)(y - 4) * K_ * K_;
        dst = xh + (size_t)(y - 4) * K_ * K_;
    }
    int i = (blockIdx.x * 256 + threadIdx.x) * 4;
    float4 v = *(const float4*)(src + i);
    uint2 o;
    o.x = pack_h2(v.x, v.y);
    o.y = pack_h2(v.z, v.w);
    *(uint2*)(dst + i) = o;
}

// ===========================================================================
// HMMA fp16 GEMM: C[m,n] = sum_k Ah[m,k]*Wh[n,k]
// Tile BM=BN=128, BK=64, 256 threads, 2 CTAs/SM, 3-stage cp.async pipeline,
// one barrier per chunk. Odd warps traverse ks in REVERSE order so LDSM
// bursts and MMA bursts overlap across warps (crossbar/tensor co-schedule).
// ===========================================================================
constexpr int RSTR     = 144;                      // smem row stride bytes
constexpr int MAT_B    = 128 * RSTR;               // 18432 bytes per matrix
constexpr int OFF_AH   = 0;
constexpr int OFF_WH   = MAT_B;
constexpr int STAGE_B  = 2 * MAT_B;                // 36864
constexpr int SMEM_GEMM = 3 * STAGE_B;             // 110592
constexpr int NCH      = K_ / 64;                  // 16

template <int MODE>
__global__ __launch_bounds__(256, 2) void gemm_mma(
    const __half* __restrict__ Ah,
    const __half* __restrict__ WhAll,
    const float* __restrict__ cosT,
    const float* __restrict__ sinT,
    float* __restrict__ Cout)
{
    extern __shared__ char dsm[];
    const uint32_t sb = smem_u32(dsm);

    const int tid    = threadIdx.x;
    const int wid    = tid >> 5;
    const int lane   = tid & 31;
    const int warp_m = wid & 1;
    const int warp_n = wid >> 1;
    const int m0     = blockIdx.y * 128;
    const int n0     = blockIdx.x * 128;
    const int z      = (MODE == 0) ? blockIdx.z : 3;

    const __half* Wh = WhAll + (size_t)z * K_ * K_;

    const int crow = tid >> 3;
    const int cseg = tid & 7;
    const uint32_t cso = (uint32_t)crow * RSTR + (uint32_t)cseg * 16;

    const int lm = lane & 7;
    const uint32_t a_off = (uint32_t)(warp_m * 64 + lm + ((lane >> 3) & 1) * 8) * RSTR
                         + (uint32_t)((lane >> 4) & 1) * 16;
    const uint32_t b_off = (uint32_t)(warp_n * 32 + lm + ((lane >> 4) & 1) * 8) * RSTR
                         + (uint32_t)((lane >> 3) & 1) * 16;

    // per-warp ks traversal order: odd warps reversed (burst desync)
    const int krev = wid & 1;

    float acc[4][4][4];
#pragma unroll
    for (int i = 0; i < 4; i++)
#pragma unroll
        for (int j = 0; j < 4; j++)
#pragma unroll
            for (int r = 0; r < 4; r++) acc[i][j][r] = 0.0f;

    auto load_stage = [&](int c, int s) {
        const uint32_t base = sb + (uint32_t)s * STAGE_B;
        const int kt0 = c * 64;
#pragma unroll
        for (int t = 0; t < 4; t++) {
            const int row = crow + 32 * t;
            size_t ao = (size_t)(m0 + row) * K_ + kt0 + cseg * 8;
            size_t wo = (size_t)(n0 + row) * K_ + kt0 + cseg * 8;
            const uint32_t so = cso + (uint32_t)(32 * t) * RSTR;
            CP_ASYNC16(base + OFF_AH + so, Ah + ao);
            CP_ASYNC16(base + OFF_WH + so, Wh + wo);
        }
        CP_COMMIT();
    };

    load_stage(0, 0);
    load_stage(1, 1);

    int sc = 0, sp = 2;
    for (int c = 0; c < NCH; c++) {
        if (c == NCH - 1) { CP_WAIT(0); } else { CP_WAIT(1); }
        __syncthreads();
        if (c + 2 < NCH) {
            load_stage(c + 2, sp);
            sp = (sp == 2) ? 0 : sp + 1;
        }

        const uint32_t base = sb + (uint32_t)sc * STAGE_B;
        sc = (sc == 2) ? 0 : sc + 1;

#pragma unroll
        for (int kk = 0; kk < 4; kk++) {
            const int ks = krev ? (3 - kk) : kk;
            const uint32_t kadd = (uint32_t)ks * 32;
            uint32_t bh[4][2];
#pragma unroll
            for (int jp = 0; jp < 4; jp += 2) {
                const uint32_t badd = b_off + (uint32_t)jp * 8 * RSTR + kadd;
                LDSM_X4(bh[jp][0], bh[jp][1], bh[jp + 1][0], bh[jp + 1][1],
                        base + OFF_WH + badd);
            }
#pragma unroll
            for (int i = 0; i < 4; i++) {
                const uint32_t aadd = a_off + (uint32_t)i * 16 * RSTR + kadd;
                uint32_t ah[4];
                LDSM_X4(ah[0], ah[1], ah[2], ah[3], base + OFF_AH + aadd);
#pragma unroll
                for (int j = 0; j < 4; j++) MMA16816H(acc[i][j], ah, bh[j]);
            }
        }
    }

    const int lr = lane >> 2;
    const int lc = (lane & 3) * 2;

    if (MODE == 0) {
        // fused epilogue, double-buffered in stage-1 smem, one sync per i-frag
        float* T = (float*)(dsm + STAGE_B);
        const int wgrp = tid >> 7;
        const int wrow = (tid >> 3) & 15;
        const int wc0  = (tid & 7) * 16;
        const int vc   = tid & 127;

#pragma unroll
        for (int i = 0; i < 4; i++) {
            float* Tb = T + (i & 1) * (2 * 16 * 132) + warp_m * (16 * 132);
#pragma unroll
            for (int rr = 0; rr < 2; rr++) {
                int row = lr + rr * 8;
#pragma unroll
                for (int j = 0; j < 4; j++) {
                    int col = warp_n * 32 + j * 8 + lc;
                    Tb[row * 132 + col]     = acc[i][j][rr * 2 + 0];
                    Tb[row * 132 + col + 1] = acc[i][j][rr * 2 + 1];
                }
            }
            __syncthreads();
            const float* Tr = T + (i & 1) * (2 * 16 * 132) + wgrp * (16 * 132);

            if (blockIdx.z == 2) {
                int n = n0 + vc, h = n >> 6, d = n & 63;
                int mbase = m0 + wgrp * 64 + i * 16;
                int b = mbase >> 11, l0i = mbase & (L_ - 1);
                __half tmp[16];
#pragma unroll
                for (int r = 0; r < 16; r++)
                    tmp[r] = __float2half_rn(Tr[r * 132 + vc]);
                size_t dst = (((size_t)(b * H_ + h)) * HD_ + d) * L_ + l0i;
                *(uint4*)&g_vth[dst]     = *(uint4*)tmp;
                *(uint4*)&g_vth[dst + 8] = *(uint4*)(tmp + 8);
            } else {
                int m = m0 + wgrp * 64 + i * 16 + wrow;
                int b = m >> 11, l = m & (L_ - 1);
                const float* crw = cosT + l * HD_;
                const float* srw = sinT + l * HD_;
                const float qsc = (blockIdx.z == 0) ? 0.125f : 1.0f;
                __half* dstbuf = (blockIdx.z == 0) ? g_qh : g_kh;
#pragma unroll
                for (int c8 = 0; c8 < 16; c8 += 8) {
                    int c = wc0 + c8;
                    __half tmp[8];
#pragma unroll
                    for (int e = 0; e < 8; e++) {
                        int cc = c + e, d = cc & 63;
                        float a  = Tr[wrow * 132 + cc];
                        float ap = Tr[wrow * 132 + (cc ^ 32)];
                        float r = (d < 32) ? a * crw[d] - ap * srw[d]
                                           : a * crw[d] + ap * srw[d];
                        tmp[e] = __float2half_rn(r * qsc);
                    }
                    int n = n0 + c, h = n >> 6, d = n & 63;
                    *(uint4*)&dstbuf[(((size_t)(b * H_ + h)) * L_ + l) * HD_ + d]
                        = *(uint4*)tmp;
                }
            }
        }
    } else {
#pragma unroll
        for (int i = 0; i < 4; i++) {
            int mr = m0 + warp_m * 64 + i * 16 + lr;
#pragma unroll
            for (int rr = 0; rr < 2; rr++) {
                int m = mr + rr * 8;
#pragma unroll
                for (int j = 0; j < 4; j++) {
                    int n = n0 + warp_n * 32 + j * 8 + lc;
                    float2 v = make_float2(acc[i][j][rr * 2 + 0], acc[i][j][rr * 2 + 1]);
                    *(float2*)&Cout[(size_t)m * D_ + n] = v;
                }
            }
        }
    }
}

// ===========================================================================
// Flash attention, fp16 single-product, 128 queries/CTA (unchanged, passing).
// ===========================================================================
constexpr int SKT = 72;

__global__ __launch_bounds__(256) void attn_mma_kernel()
{
    __shared__ __half sK[64 * SKT], sV[64 * SKT];

    const int tid  = threadIdx.x;
    const int wid  = tid >> 5;
    const int lane = tid & 31;
    const int lr   = lane >> 2;
    const int kp   = (lane & 3) * 2;

    const int bh = blockIdx.x;
    const int q0 = blockIdx.y * 128;

    const __half* qb  = g_qh  + ((size_t)bh * L_ + q0) * HD_;
    const __half* kb  = g_kh  + (size_t)bh * L_ * HD_;
    const __half* vtb = g_vth + (size_t)bh * HD_ * L_;

    uint32_t qh[4][4];
#pragma unroll
    for (int ks = 0; ks < 4; ks++) {
#pragma unroll
        for (int e = 0; e < 4; e++) {
            int row  = wid * 16 + lr + (e & 1) * 8;
            int kcol = ks * 16 + kp + (e >= 2 ? 8 : 0);
            qh[ks][e] = *(const uint32_t*)(qb + (size_t)row * HD_ + kcol);
        }
    }

    float o[8][4];
#pragma unroll
    for (int f = 0; f < 8; f++)
#pragma unroll
        for (int e = 0; e < 4; e++) o[f][e] = 0.0f;
    float m0 = -1e30f, m1 = -1e30f, sum0 = 0.0f, sum1 = 0.0f;

    const int rowa = q0 + wid * 16 + lr;
    const int wmin = q0 + wid * 16;
    const int wmax = wmin + 15;
    const int j0s  = (q0 - WIN_ > 0) ? (q0 - WIN_) : 0;

    for (int j0 = j0s; j0 <= q0 + 64; j0 += 64) {
        {
            const int r  = tid >> 2;
            const int cb = (tid & 3) * 16;
            const uint4* ks4 = (const uint4*)(kb  + (size_t)(j0 + r) * HD_ + cb);
            const uint4* vs4 = (const uint4*)(vtb + (size_t)r * L_ + j0 + cb);
            uint4* kd4 = (uint4*)(sK + r * SKT + cb);
            uint4* vd4 = (uint4*)(sV + r * SKT + cb);
            kd4[0] = ks4[0]; kd4[1] = ks4[1];
            vd4[0] = vs4[0]; vd4[1] = vs4[1];
        }
        __syncthreads();

        const bool active = (j0 <= wmax) && (j0 + 63 >= wmin - WIN_);
        if (active) {
            float sf[8][4];
#pragma unroll
            for (int f = 0; f < 8; f++)
#pragma unroll
                for (int e = 0; e < 4; e++) sf[f][e] = 0.0f;

#pragma unroll
            for (int ks = 0; ks < 4; ks++) {
#pragma unroll
                for (int f = 0; f < 8; f++) {
                    const int nrow = f * 8 + lr;
                    const int kc   = ks * 16 + kp;
                    uint32_t kf[2];
                    kf[0] = *(const uint32_t*)(sK + nrow * SKT + kc);
                    kf[1] = *(const uint32_t*)(sK + nrow * SKT + kc + 8);
                    MMA16816H(sf[f], qh[ks], kf);
                }
            }

            const bool full = (j0 + 63 <= wmin) && (j0 >= wmax - WIN_);
            if (!full) {
#pragma unroll
                for (int f = 0; f < 8; f++) {
#pragma unroll
                    for (int e = 0; e < 4; e++) {
                        const int col = j0 + f * 8 + kp + (e & 1);
                        const int row = rowa + (e >= 2 ? 8 : 0);
                        const bool ok = (col <= row) && (col >= row - WIN_);
                        if (!ok) sf[f][e] = -1e30f;
                    }
                }
            }

            float rm0 = -1e30f, rm1 = -1e30f;
#pragma unroll
            for (int f = 0; f < 8; f++) {
                rm0 = fmaxf(rm0, fmaxf(sf[f][0], sf[f][1]));
                rm1 = fmaxf(rm1, fmaxf(sf[f][2], sf[f][3]));
            }
            rm0 = fmaxf(rm0, __shfl_xor_sync(0xFFFFFFFFu, rm0, 1));
            rm0 = fmaxf(rm0, __shfl_xor_sync(0xFFFFFFFFu, rm0, 2));
            rm1 = fmaxf(rm1, __shfl_xor_sync(0xFFFFFFFFu, rm1, 1));
            rm1 = fmaxf(rm1, __shfl_xor_sync(0xFFFFFFFFu, rm1, 2));

            const float mn0 = fmaxf(m0, rm0);
            const float mn1 = fmaxf(m1, rm1);
            const float sc0 = __expf(m0 - mn0);
            const float sc1 = __expf(m1 - mn1);

            float rs0 = 0.0f, rs1 = 0.0f;
#pragma unroll
            for (int f = 0; f < 8; f++) {
                sf[f][0] = __expf(sf[f][0] - mn0);
                sf[f][1] = __expf(sf[f][1] - mn0);
                sf[f][2] = __expf(sf[f][2] - mn1);
                sf[f][3] = __expf(sf[f][3] - mn1);
                rs0 += sf[f][0] + sf[f][1];
                rs1 += sf[f][2] + sf[f][3];
            }
            rs0 += __shfl_xor_sync(0xFFFFFFFFu, rs0, 1);
            rs0 += __shfl_xor_sync(0xFFFFFFFFu, rs0, 2);
            rs1 += __shfl_xor_sync(0xFFFFFFFFu, rs1, 1);
            rs1 += __shfl_xor_sync(0xFFFFFFFFu, rs1, 2);

            sum0 = sum0 * sc0 + rs0;
            sum1 = sum1 * sc1 + rs1;
            m0 = mn0;
            m1 = mn1;
#pragma unroll
            for (int f = 0; f < 8; f++) {
                o[f][0] *= sc0;
                o[f][1] *= sc0;
                o[f][2] *= sc1;
                o[f][3] *= sc1;
            }

#pragma unroll
            for (int ks = 0; ks < 4; ks++) {
                uint32_t ph[4];
                ph[0] = pack_h2(sf[2 * ks][0],     sf[2 * ks][1]);
                ph[1] = pack_h2(sf[2 * ks][2],     sf[2 * ks][3]);
                ph[2] = pack_h2(sf[2 * ks + 1][0], sf[2 * ks + 1][1]);
                ph[3] = pack_h2(sf[2 * ks + 1][2], sf[2 * ks + 1][3]);
#pragma unroll
                for (int f = 0; f < 8; f++) {
                    const int nrow = f * 8 + lr;
                    const int kc   = ks * 16 + kp;
                    uint32_t vf[2];
                    vf[0] = *(const uint32_t*)(sV + nrow * SKT + kc);
                    vf[1] = *(const uint32_t*)(sV + nrow * SKT + kc + 8);
                    MMA16816H(o[f], ph, vf);
                }
            }
        }
        __syncthreads();
    }

    const float inv0 = 1.0f / sum0;
    const float inv1 = 1.0f / sum1;
    const int b = bh >> 4;
    const int h = bh & (H_ - 1);
#pragma unroll
    for (int f = 0; f < 8; f++) {
        const int d = f * 8 + kp;
        const size_t i0 = ((size_t)(b * L_ + rowa)) * D_ + h * HD_ + d;
        const size_t i1 = ((size_t)(b * L_ + rowa + 8)) * D_ + h * HD_ + d;
        *(uint32_t*)&g_oh[i0] = pack_h2(o[f][0] * inv0, o[f][1] * inv0);
        *(uint32_t*)&g_oh[i1] = pack_h2(o[f][2] * inv1, o[f][3] * inv1);
    }
}

// ---------------------------------------------------------------------------
extern "C" void kernel_launch(void* const* d_in, const int* in_sizes, int n_in,
                              void* d_out, int out_size)
{
    const float* x    = (const float*)d_in[0];
    const float* cosT = (const float*)d_in[1];
    const float* sinT = (const float*)d_in[2];
    const float* Wq   = (const float*)d_in[3];
    const float* Wk   = (const float*)d_in[4];
    const float* Wv   = (const float*)d_in[5];
    const float* Wo   = (const float*)d_in[6];
    float* out        = (float*)d_out;

    cudaFuncSetAttribute(gemm_mma<0>, cudaFuncAttributeMaxDynamicSharedMemorySize, SMEM_GEMM);
    cudaFuncSetAttribute(gemm_mma<1>, cudaFuncAttributeMaxDynamicSharedMemorySize, SMEM_GEMM);

    __half *xh, *wh, *oh;
    cudaGetSymbolAddress((void**)&xh, g_xh);
    cudaGetSymbolAddress((void**)&wh, g_wh);
    cudaGetSymbolAddress((void**)&oh, g_oh);

    // 1) convert x and all W's to fp16 (one launch)
    convert_all_kernel<<<dim3((K_ * K_) / 1024, 8), 256>>>(x, Wq, Wk, Wv, Wo, wh, xh);

    // 2) QKV projection + fused RoPE / V-transpose epilogue (all fp16 out)
    gemm_mma<0><<<dim3(D_ / 128, M_ / 128, 3), 256, SMEM_GEMM>>>(
        xh, wh, cosT, sinT, nullptr);

    // 3) Flash attention (fp16, single-product, 128 queries/CTA)
    attn_mma_kernel<<<dim3(B_ * H_, L_ / 128), 256>>>();

    // 4) Output projection
    gemm_mma<1><<<dim3(D_ / 128, M_ / 128, 1), 256, SMEM_GEMM>>>(
        oh, wh, nullptr, nullptr, out);
}

// round 16
// speedup vs baseline: 1.0308x; 1.0308x over previous
#include <cuda_runtime.h>
#include <cuda_fp16.h>
#include <math.h>
#include <stdint.h>

// Problem constants
constexpr int B_   = 2;
constexpr int L_   = 2048;
constexpr int D_   = 1024;
constexpr int H_   = 16;
constexpr int HD_  = 64;
constexpr int WIN_ = 256;
constexpr int M_   = B_ * L_;   // 4096 rows
constexpr int K_   = D_;        // 1024 reduction dim

// Scratch (allocation-free: __device__ globals)
__device__ __half g_qh [(size_t)B_ * H_ * L_ * HD_];   // q fp16, roped, pre-scaled 1/8
__device__ __half g_kh [(size_t)B_ * H_ * L_ * HD_];   // k fp16, roped
__device__ __half g_vth[(size_t)B_ * H_ * HD_ * L_];   // v fp16 transposed [b,h,d,l]

__device__ __half g_xh [(size_t)M_ * K_];
__device__ __half g_wh [(size_t)4 * K_ * K_];          // Wq,Wk,Wv,Wo fp16
__device__ __half g_oh [(size_t)M_ * K_];              // attn out fp16

// fp16 m16n8k16 mma (baseline PTX, works on plain sm_103 target)
#define MMA16816H(d, a, b) \
    asm volatile("mma.sync.aligned.m16n8k16.row.col.f32.f16.f16.f32 " \
        "{%0,%1,%2,%3}, {%4,%5,%6,%7}, {%8,%9}, {%0,%1,%2,%3};" \
        : "+f"((d)[0]), "+f"((d)[1]), "+f"((d)[2]), "+f"((d)[3]) \
        : "r"((a)[0]), "r"((a)[1]), "r"((a)[2]), "r"((a)[3]), \
          "r"((b)[0]), "r"((b)[1]))

#define LDSM_X4(r0, r1, r2, r3, addr) \
    asm volatile("ldmatrix.sync.aligned.m8n8.x4.shared.b16 {%0,%1,%2,%3}, [%4];" \
        : "=r"(r0), "=r"(r1), "=r"(r2), "=r"(r3) : "r"(addr))

#define CP_ASYNC16(smaddr, gptr) \
    asm volatile("cp.async.cg.shared.global [%0], [%1], 16;" :: "r"(smaddr), "l"(gptr))
#define CP_COMMIT() asm volatile("cp.async.commit_group;" ::: "memory")
#define CP_WAIT(n)  asm volatile("cp.async.wait_group %0;" :: "n"(n) : "memory")

__device__ __forceinline__ uint32_t smem_u32(const void* p) {
    uint32_t a;
    asm("{ .reg .u64 t; cvta.to.shared.u64 t, %1; cvt.u32.u64 %0, t; }" : "=r"(a) : "l"(p));
    return a;
}
__device__ __forceinline__ uint32_t pack_h2(float a, float b) {
    __half2 h = __floats2half2_rn(a, b);
    return *(uint32_t*)&h;
}

// ===========================================================================
// convert x (4 chunks) + all 4 W's to fp16 in ONE launch. grid=(1024, 8).
// ===========================================================================
__global__ __launch_bounds__(256) void convert_all_kernel(
    const float* __restrict__ x,
    const float* __restrict__ W0, const float* __restrict__ W1,
    const float* __restrict__ W2, const float* __restrict__ W3,
    __half* __restrict__ wh, __half* __restrict__ xh)
{
    const int y = blockIdx.y;
    const float* src;
    __half* dst;
    if (y < 4) {
        src = (y == 0) ? W0 : (y == 1) ? W1 : (y == 2) ? W2 : W3;
        dst = wh + (size_t)y * K_ * K_;
    } else {
        src = x + (size_t)(y - 4) * K_ * K_;
        dst = xh + (size_t)(y - 4) * K_ * K_;
    }
    int i = (blockIdx.x * 256 + threadIdx.x) * 4;
    float4 v = *(const float4*)(src + i);
    uint2 o;
    o.x = pack_h2(v.x, v.y);
    o.y = pack_h2(v.z, v.w);
    *(uint2*)(dst + i) = o;
}

// ===========================================================================
// HMMA fp16 GEMM (exact R13 configuration — measured 176.6us baseline):
// Tile BM=BN=128, BK=64, 256 threads, 2 CTAs/SM, 3-stage cp.async pipeline,
// one barrier per chunk.
// ===========================================================================
constexpr int RSTR     = 144;                      // smem row stride bytes
constexpr int MAT_B    = 128 * RSTR;               // 18432 bytes per matrix
constexpr int OFF_AH   = 0;
constexpr int OFF_WH   = MAT_B;
constexpr int STAGE_B  = 2 * MAT_B;                // 36864
constexpr int SMEM_GEMM = 3 * STAGE_B;             // 110592
constexpr int NCH      = K_ / 64;                  // 16

template <int MODE>
__global__ __launch_bounds__(256, 2) void gemm_mma(
    const __half* __restrict__ Ah,
    const __half* __restrict__ WhAll,
    const float* __restrict__ cosT,
    const float* __restrict__ sinT,
    float* __restrict__ Cout)
{
    extern __shared__ char dsm[];
    const uint32_t sb = smem_u32(dsm);

    const int tid    = threadIdx.x;
    const int wid    = tid >> 5;
    const int lane   = tid & 31;
    const int warp_m = wid & 1;
    const int warp_n = wid >> 1;
    const int m0     = blockIdx.y * 128;
    const int n0     = blockIdx.x * 128;
    const int z      = (MODE == 0) ? blockIdx.z : 3;

    const __half* Wh = WhAll + (size_t)z * K_ * K_;

    const int crow = tid >> 3;
    const int cseg = tid & 7;
    const uint32_t cso = (uint32_t)crow * RSTR + (uint32_t)cseg * 16;

    const int lm = lane & 7;
    const uint32_t a_off = (uint32_t)(warp_m * 64 + lm + ((lane >> 3) & 1) * 8) * RSTR
                         + (uint32_t)((lane >> 4) & 1) * 16;
    const uint32_t b_off = (uint32_t)(warp_n * 32 + lm + ((lane >> 4) & 1) * 8) * RSTR
                         + (uint32_t)((lane >> 3) & 1) * 16;

    float acc[4][4][4];
#pragma unroll
    for (int i = 0; i < 4; i++)
#pragma unroll
        for (int j = 0; j < 4; j++)
#pragma unroll
            for (int r = 0; r < 4; r++) acc[i][j][r] = 0.0f;

    auto load_stage = [&](int c, int s) {
        const uint32_t base = sb + (uint32_t)s * STAGE_B;
        const int kt0 = c * 64;
#pragma unroll
        for (int t = 0; t < 4; t++) {
            const int row = crow + 32 * t;
            size_t ao = (size_t)(m0 + row) * K_ + kt0 + cseg * 8;
            size_t wo = (size_t)(n0 + row) * K_ + kt0 + cseg * 8;
            const uint32_t so = cso + (uint32_t)(32 * t) * RSTR;
            CP_ASYNC16(base + OFF_AH + so, Ah + ao);
            CP_ASYNC16(base + OFF_WH + so, Wh + wo);
        }
        CP_COMMIT();
    };

    load_stage(0, 0);
    load_stage(1, 1);

    int sc = 0, sp = 2;
    for (int c = 0; c < NCH; c++) {
        if (c == NCH - 1) { CP_WAIT(0); } else { CP_WAIT(1); }
        __syncthreads();
        if (c + 2 < NCH) {
            load_stage(c + 2, sp);
            sp = (sp == 2) ? 0 : sp + 1;
        }

        const uint32_t base = sb + (uint32_t)sc * STAGE_B;
        sc = (sc == 2) ? 0 : sc + 1;

#pragma unroll
        for (int ks = 0; ks < 4; ks++) {
            const uint32_t kadd = (uint32_t)ks * 32;
            uint32_t bh[4][2];
#pragma unroll
            for (int jp = 0; jp < 4; jp += 2) {
                const uint32_t badd = b_off + (uint32_t)jp * 8 * RSTR + kadd;
                LDSM_X4(bh[jp][0], bh[jp][1], bh[jp + 1][0], bh[jp + 1][1],
                        base + OFF_WH + badd);
            }
#pragma unroll
            for (int i = 0; i < 4; i++) {
                const uint32_t aadd = a_off + (uint32_t)i * 16 * RSTR + kadd;
                uint32_t ah[4];
                LDSM_X4(ah[0], ah[1], ah[2], ah[3], base + OFF_AH + aadd);
#pragma unroll
                for (int j = 0; j < 4; j++) MMA16816H(acc[i][j], ah, bh[j]);
            }
        }
    }

    const int lr = lane >> 2;
    const int lc = (lane & 3) * 2;

    if (MODE == 0) {
        // fused epilogue, double-buffered in stage-1 smem, one sync per i-frag
        float* T = (float*)(dsm + STAGE_B);
        const int wgrp = tid >> 7;
        const int wrow = (tid >> 3) & 15;
        const int wc0  = (tid & 7) * 16;
        const int vc   = tid & 127;

#pragma unroll
        for (int i = 0; i < 4; i++) {
            float* Tb = T + (i & 1) * (2 * 16 * 132) + warp_m * (16 * 132);
#pragma unroll
            for (int rr = 0; rr < 2; rr++) {
                int row = lr + rr * 8;
#pragma unroll
                for (int j = 0; j < 4; j++) {
                    int col = warp_n * 32 + j * 8 + lc;
                    Tb[row * 132 + col]     = acc[i][j][rr * 2 + 0];
                    Tb[row * 132 + col + 1] = acc[i][j][rr * 2 + 1];
                }
            }
            __syncthreads();
            const float* Tr = T + (i & 1) * (2 * 16 * 132) + wgrp * (16 * 132);

            if (blockIdx.z == 2) {
                int n = n0 + vc, h = n >> 6, d = n & 63;
                int mbase = m0 + wgrp * 64 + i * 16;
                int b = mbase >> 11, l0i = mbase & (L_ - 1);
                __half tmp[16];
#pragma unroll
                for (int r = 0; r < 16; r++)
                    tmp[r] = __float2half_rn(Tr[r * 132 + vc]);
                size_t dst = (((size_t)(b * H_ + h)) * HD_ + d) * L_ + l0i;
                *(uint4*)&g_vth[dst]     = *(uint4*)tmp;
                *(uint4*)&g_vth[dst + 8] = *(uint4*)(tmp + 8);
            } else {
                int m = m0 + wgrp * 64 + i * 16 + wrow;
                int b = m >> 11, l = m & (L_ - 1);
                const float* crw = cosT + l * HD_;
                const float* srw = sinT + l * HD_;
                const float qsc = (blockIdx.z == 0) ? 0.125f : 1.0f;
                __half* dstbuf = (blockIdx.z == 0) ? g_qh : g_kh;
#pragma unroll
                for (int c8 = 0; c8 < 16; c8 += 8) {
                    int c = wc0 + c8;
                    __half tmp[8];
#pragma unroll
                    for (int e = 0; e < 8; e++) {
                        int cc = c + e, d = cc & 63;
                        float a  = Tr[wrow * 132 + cc];
                        float ap = Tr[wrow * 132 + (cc ^ 32)];
                        float r = (d < 32) ? a * crw[d] - ap * srw[d]
                                           : a * crw[d] + ap * srw[d];
                        tmp[e] = __float2half_rn(r * qsc);
                    }
                    int n = n0 + c, h = n >> 6, d = n & 63;
                    *(uint4*)&dstbuf[(((size_t)(b * H_ + h)) * L_ + l) * HD_ + d]
                        = *(uint4*)tmp;
                }
            }
        }
    } else {
#pragma unroll
        for (int i = 0; i < 4; i++) {
            int mr = m0 + warp_m * 64 + i * 16 + lr;
#pragma unroll
            for (int rr = 0; rr < 2; rr++) {
                int m = mr + rr * 8;
#pragma unroll
                for (int j = 0; j < 4; j++) {
                    int n = n0 + warp_n * 32 + j * 8 + lc;
                    float2 v = make_float2(acc[i][j][rr * 2 + 0], acc[i][j][rr * 2 + 1]);
                    *(float2*)&Cout[(size_t)m * D_ + n] = v;
                }
            }
        }
    }
}

// ===========================================================================
// Flash attention, fp16 single-product, 128 queries/CTA.
// K/V chunk loads now cp.async double-buffered: global-load latency hides
// behind the previous chunk's compute. Same 2 barriers per chunk.
// ===========================================================================
constexpr int SKT   = 72;
constexpr int KVBUF = 64 * SKT;      // halves per buffer

__global__ __launch_bounds__(256) void attn_mma_kernel()
{
    __shared__ __half sK[2][KVBUF], sV[2][KVBUF];

    const int tid  = threadIdx.x;
    const int wid  = tid >> 5;
    const int lane = tid & 31;
    const int lr   = lane >> 2;
    const int kp   = (lane & 3) * 2;

    const int bh = blockIdx.x;
    const int q0 = blockIdx.y * 128;

    const __half* qb  = g_qh  + ((size_t)bh * L_ + q0) * HD_;
    const __half* kb  = g_kh  + (size_t)bh * L_ * HD_;
    const __half* vtb = g_vth + (size_t)bh * HD_ * L_;

    const uint32_t skb = smem_u32(sK);
    const uint32_t svb = smem_u32(sV);

    // cp.async K/V chunk load: thread covers 32B of K and 32B of V
    const int rkv = tid >> 2;
    const int ckv = (tid & 3) * 16;
    const uint32_t skvo = ((uint32_t)rkv * SKT + (uint32_t)ckv) * 2;
    auto load_kv = [&](int j0, int s) {
        const __half* kg = kb  + (size_t)(j0 + rkv) * HD_ + ckv;
        const __half* vg = vtb + (size_t)rkv * L_ + j0 + ckv;
        const uint32_t kd = skb + (uint32_t)s * (KVBUF * 2) + skvo;
        const uint32_t vd = svb + (uint32_t)s * (KVBUF * 2) + skvo;
        CP_ASYNC16(kd,      kg);
        CP_ASYNC16(kd + 16, kg + 8);
        CP_ASYNC16(vd,      vg);
        CP_ASYNC16(vd + 16, vg + 8);
        CP_COMMIT();
    };

    // Q fragments (warp owns rows q0 + wid*16 .. +15)
    uint32_t qh[4][4];
#pragma unroll
    for (int ks = 0; ks < 4; ks++) {
#pragma unroll
        for (int e = 0; e < 4; e++) {
            int row  = wid * 16 + lr + (e & 1) * 8;
            int kcol = ks * 16 + kp + (e >= 2 ? 8 : 0);
            qh[ks][e] = *(const uint32_t*)(qb + (size_t)row * HD_ + kcol);
        }
    }

    float o[8][4];
#pragma unroll
    for (int f = 0; f < 8; f++)
#pragma unroll
        for (int e = 0; e < 4; e++) o[f][e] = 0.0f;
    float m0 = -1e30f, m1 = -1e30f, sum0 = 0.0f, sum1 = 0.0f;

    const int rowa = q0 + wid * 16 + lr;
    const int wmin = q0 + wid * 16;
    const int wmax = wmin + 15;
    const int j0s  = (q0 - WIN_ > 0) ? (q0 - WIN_) : 0;
    const int nch  = (q0 + 64 - j0s) / 64 + 1;

    load_kv(j0s, 0);

    for (int t = 0; t < nch; t++) {
        const int j0 = j0s + t * 64;
        if (t + 1 < nch) { load_kv(j0 + 64, (t + 1) & 1); CP_WAIT(1); }
        else             { CP_WAIT(0); }
        __syncthreads();

        const __half* sKp = sK[t & 1];
        const __half* sVp = sV[t & 1];

        const bool active = (j0 <= wmax) && (j0 + 63 >= wmin - WIN_);
        if (active) {
            float sf[8][4];
#pragma unroll
            for (int f = 0; f < 8; f++)
#pragma unroll
                for (int e = 0; e < 4; e++) sf[f][e] = 0.0f;

#pragma unroll
            for (int ks = 0; ks < 4; ks++) {
#pragma unroll
                for (int f = 0; f < 8; f++) {
                    const int nrow = f * 8 + lr;
                    const int kc   = ks * 16 + kp;
                    uint32_t kf[2];
                    kf[0] = *(const uint32_t*)(sKp + nrow * SKT + kc);
                    kf[1] = *(const uint32_t*)(sKp + nrow * SKT + kc + 8);
                    MMA16816H(sf[f], qh[ks], kf);
                }
            }

            const bool full = (j0 + 63 <= wmin) && (j0 >= wmax - WIN_);
            if (!full) {
#pragma unroll
                for (int f = 0; f < 8; f++) {
#pragma unroll
                    for (int e = 0; e < 4; e++) {
                        const int col = j0 + f * 8 + kp + (e & 1);
                        const int row = rowa + (e >= 2 ? 8 : 0);
                        const bool ok = (col <= row) && (col >= row - WIN_);
                        if (!ok) sf[f][e] = -1e30f;
                    }
                }
            }

            float rm0 = -1e30f, rm1 = -1e30f;
#pragma unroll
            for (int f = 0; f < 8; f++) {
                rm0 = fmaxf(rm0, fmaxf(sf[f][0], sf[f][1]));
                rm1 = fmaxf(rm1, fmaxf(sf[f][2], sf[f][3]));
            }
            rm0 = fmaxf(rm0, __shfl_xor_sync(0xFFFFFFFFu, rm0, 1));
            rm0 = fmaxf(rm0, __shfl_xor_sync(0xFFFFFFFFu, rm0, 2));
            rm1 = fmaxf(rm1, __shfl_xor_sync(0xFFFFFFFFu, rm1, 1));
            rm1 = fmaxf(rm1, __shfl_xor_sync(0xFFFFFFFFu, rm1, 2));

            const float mn0 = fmaxf(m0, rm0);
            const float mn1 = fmaxf(m1, rm1);
            const float sc0 = __expf(m0 - mn0);
            const float sc1 = __expf(m1 - mn1);

            float rs0 = 0.0f, rs1 = 0.0f;
#pragma unroll
            for (int f = 0; f < 8; f++) {
                sf[f][0] = __expf(sf[f][0] - mn0);
                sf[f][1] = __expf(sf[f][1] - mn0);
                sf[f][2] = __expf(sf[f][2] - mn1);
                sf[f][3] = __expf(sf[f][3] - mn1);
                rs0 += sf[f][0] + sf[f][1];
                rs1 += sf[f][2] + sf[f][3];
            }
            rs0 += __shfl_xor_sync(0xFFFFFFFFu, rs0, 1);
            rs0 += __shfl_xor_sync(0xFFFFFFFFu, rs0, 2);
            rs1 += __shfl_xor_sync(0xFFFFFFFFu, rs1, 1);
            rs1 += __shfl_xor_sync(0xFFFFFFFFu, rs1, 2);

            sum0 = sum0 * sc0 + rs0;
            sum1 = sum1 * sc1 + rs1;
            m0 = mn0;
            m1 = mn1;
#pragma unroll
            for (int f = 0; f < 8; f++) {
                o[f][0] *= sc0;
                o[f][1] *= sc0;
                o[f][2] *= sc1;
                o[f][3] *= sc1;
            }

#pragma unroll
            for (int ks = 0; ks < 4; ks++) {
                uint32_t ph[4];
                ph[0] = pack_h2(sf[2 * ks][0],     sf[2 * ks][1]);
                ph[1] = pack_h2(sf[2 * ks][2],     sf[2 * ks][3]);
                ph[2] = pack_h2(sf[2 * ks + 1][0], sf[2 * ks + 1][1]);
                ph[3] = pack_h2(sf[2 * ks + 1][2], sf[2 * ks + 1][3]);
#pragma unroll
                for (int f = 0; f < 8; f++) {
                    const int nrow = f * 8 + lr;
                    const int kc   = ks * 16 + kp;
                    uint32_t vf[2];
                    vf[0] = *(const uint32_t*)(sVp + nrow * SKT + kc);
                    vf[1] = *(const uint32_t*)(sVp + nrow * SKT + kc + 8);
                    MMA16816H(o[f], ph, vf);
                }
            }
        }
        __syncthreads();
    }

    // epilogue: normalize, emit fp16 for output projection
    const float inv0 = 1.0f / sum0;
    const float inv1 = 1.0f / sum1;
    const int b = bh >> 4;
    const int h = bh & (H_ - 1);
#pragma unroll
    for (int f = 0; f < 8; f++) {
        const int d = f * 8 + kp;
        const size_t i0 = ((size_t)(b * L_ + rowa)) * D_ + h * HD_ + d;
        const size_t i1 = ((size_t)(b * L_ + rowa + 8)) * D_ + h * HD_ + d;
        *(uint32_t*)&g_oh[i0] = pack_h2(o[f][0] * inv0, o[f][1] * inv0);
        *(uint32_t*)&g_oh[i1] = pack_h2(o[f][2] * inv1, o[f][3] * inv1);
    }
}

// ---------------------------------------------------------------------------
extern "C" void kernel_launch(void* const* d_in, const int* in_sizes, int n_in,
                              void* d_out, int out_size)
{
    const float* x    = (const float*)d_in[0];
    const float* cosT = (const float*)d_in[1];
    const float* sinT = (const float*)d_in[2];
    const float* Wq   = (const float*)d_in[3];
    const float* Wk   = (const float*)d_in[4];
    const float* Wv   = (const float*)d_in[5];
    const float* Wo   = (const float*)d_in[6];
    float* out        = (float*)d_out;

    cudaFuncSetAttribute(gemm_mma<0>, cudaFuncAttributeMaxDynamicSharedMemorySize, SMEM_GEMM);
    cudaFuncSetAttribute(gemm_mma<1>, cudaFuncAttributeMaxDynamicSharedMemorySize, SMEM_GEMM);

    __half *xh, *wh, *oh;
    cudaGetSymbolAddress((void**)&xh, g_xh);
    cudaGetSymbolAddress((void**)&wh, g_wh);
    cudaGetSymbolAddress((void**)&oh, g_oh);

    // 1) convert x and all W's to fp16 (one launch)
    convert_all_kernel<<<dim3((K_ * K_) / 1024, 8), 256>>>(x, Wq, Wk, Wv, Wo, wh, xh);

    // 2) QKV projection + fused RoPE / V-transpose epilogue (all fp16 out)
    gemm_mma<0><<<dim3(D_ / 128, M_ / 128, 3), 256, SMEM_GEMM>>>(
        xh, wh, cosT, sinT, nullptr);

    // 3) Flash attention (fp16, single-product, 128 queries/CTA, cp.async KV)
    attn_mma_kernel<<<dim3(B_ * H_, L_ / 128), 256>>>();

    // 4) Output projection
    gemm_mma<1><<<dim3(D_ / 128, M_ / 128, 1), 256, SMEM_GEMM>>>(
        oh, wh, nullptr, nullptr, out);
}